// round 14
// baseline (speedup 1.0000x reference)
#include <cuda_runtime.h>
#include <math.h>

// ---------------- problem constants ----------------
#define N_CH   256
#define T_IN   100000
#define L1_LEN 20000
#define L2_LEN 4000
#define L3_LEN 800
#define CNN_OUT 32
#define GRU_H   64

// conv fused tiling
#define TILE   20
#define NTILE  (L3_LEN / TILE)
#define C2_SPAN 100
#define C1_SPAN 502

#define INP_ROW 508
#define C1_ROW  104
#define C2_ROW  20

// interleaved conv-weight table
#define W1I_OFF 0
#define W2I_OFF 88
#define W3I_OFF 984
#define WCONV_TOT 3544

// GRU gi chunking
#define GCH 4                      // steps per staged chunk
#define SEQ_STRIDE (800 * 192)     // floats per sequence in g_gi

typedef unsigned long long ULL;

// ---------------- f32x2 helpers ----------------
__device__ __forceinline__ ULL pk2(float a, float b) {
    ULL r; asm("mov.b64 %0, {%1, %2};" : "=l"(r) : "f"(a), "f"(b)); return r;
}
__device__ __forceinline__ void upk2(ULL v, float &a, float &b) {
    asm("mov.b64 {%0, %1}, %2;" : "=f"(a), "=f"(b) : "l"(v));
}
__device__ __forceinline__ void fma2(ULL &d, ULL a, ULL b) {
    asm("fma.rn.f32x2 %0, %1, %2, %0;" : "+l"(d) : "l"(a), "l"(b));
}

__device__ __forceinline__ float sigmoid_f(float x) {
    return __fdividef(1.f, 1.f + __expf(-x));
}
__device__ __forceinline__ float tanh_f(float x) {
    return 1.f - __fdividef(2.f, __expf(2.f * x) + 1.f);
}

// ---------------- scratch (static device, no allocation) ----------------
__device__ __align__(16) float g_wconv[WCONV_TOT];
__device__ __align__(16) float g_gi[512 * SEQ_STRIDE];   // gi[seq][step][row] (315MB)
__device__ float g_hn[N_CH * 128];
__device__ float g_xnT[128 * N_CH];
__device__ float g_A[N_CH * N_CH];
__device__ float g_dinv[N_CH];
__device__ float g_M1[N_CH * 32];
__device__ float g_M2[N_CH * 32];
__device__ float g_h2[N_CH * 32];

// =====================================================================
// Prep kernels: interleave conv weights once (3 kernels so the ncu
// capture slot #4 lands on the fused conv kernel)
// =====================================================================
__global__ void k_prep1(const float* __restrict__ w1)
{
    const int tid = threadIdx.x;
    if (tid < 44) {
        int pr = tid / 11, k = tid - pr * 11;
        g_wconv[W1I_OFF + 2*tid]     = w1[(2*pr)   * 11 + k];
        g_wconv[W1I_OFF + 2*tid + 1] = w1[(2*pr+1) * 11 + k];
    }
}
__global__ void k_prep2(const float* __restrict__ w2)
{
    const int tid = threadIdx.x;
    for (int i = tid; i < 448; i += 256) {
        int k = i % 7, ic = (i / 7) % 8, pr = i / 56;
        g_wconv[W2I_OFF + 2*i]     = w2[((2*pr)   * 8 + ic) * 7 + k];
        g_wconv[W2I_OFF + 2*i + 1] = w2[((2*pr+1) * 8 + ic) * 7 + k];
    }
}
__global__ void k_prep3(const float* __restrict__ w3)
{
    const int tid = threadIdx.x;
    for (int i = tid; i < 1280; i += 256) {
        int k = i % 5, ic = (i / 5) % 16, pr = i / 80;
        g_wconv[W3I_OFF + 2*i]     = w3[((2*pr)   * 16 + ic) * 5 + k];
        g_wconv[W3I_OFF + 2*i + 1] = w3[((2*pr+1) * 16 + ic) * 5 + k];
    }
}

// =====================================================================
// Kernel: fused conv1+conv2+conv3 + gi epilogue
// (x tile stays in smem; gi written directly; g_x3 eliminated)
// =====================================================================
#define SM_INP  0
#define SM_C1P  (SM_INP + 5*INP_ROW)       // reused as x-buffer in gi phase
#define SM_C2P  (SM_C1P + 5*8*C1_ROW)
#define SM_W1   (SM_C2P + 5*16*C2_ROW)
#define SM_W2   (SM_W1 + 88)
#define SM_W3   (SM_W2 + 896)
#define SM_B1   (SM_W3 + 2560)
#define SM_B2   (SM_B1 + 8)
#define SM_B3   (SM_B2 + 16)
#define SM_TOT  (SM_B3 + 32)

__global__ __launch_bounds__(256) void k_conv_fused(
    const float* __restrict__ data,
    const float* __restrict__ b1,
    const float* __restrict__ b2,
    const float* __restrict__ b3,
    const float* __restrict__ wih_f, const float* __restrict__ bih_f,
    const float* __restrict__ wih_b, const float* __restrict__ bih_b)
{
    __shared__ __align__(16) float sm[SM_TOT];

    const int tid = threadIdx.x;
    const int c   = blockIdx.x / NTILE;
    const int t0  = (blockIdx.x % NTILE) * TILE;

    {
        const float4* src = (const float4*)g_wconv;
        float4* dst = (float4*)(sm + SM_W1);
        for (int i = tid; i < WCONV_TOT / 4; i += 256) dst[i] = src[i];
    }
    if (tid < 8)  sm[SM_B1 + tid] = b1[tid];
    if (tid < 16) sm[SM_B2 + tid] = b2[tid];
    if (tid < 32) sm[SM_B3 + tid] = b3[tid];

    {
        const float* dch = data + (size_t)c * T_IN;
        const int base = 125 * t0 - 70;
        for (int i = tid; i < 5 * INP_ROW; i += 256) {
            int g = base + i;
            float v = (g >= 0 && g < T_IN) ? dch[g] : 0.f;
            sm[SM_INP + (i % 5) * INP_ROW + (i / 5)] = v;
        }
    }
    __syncthreads();

    // conv1
    {
        const int grp = tid >> 6;
        const int l64 = tid & 63;
        ULL wreg[11];
        {
            const ULL* wp = (const ULL*)(sm + SM_W1) + grp * 11;
            #pragma unroll
            for (int k = 0; k < 11; k++) wreg[k] = wp[k];
        }
        const ULL bpair = pk2(sm[SM_B1 + 2*grp], sm[SM_B1 + 2*grp + 1]);
        const int q0g = 25 * t0 - 13;

        #pragma unroll
        for (int it = 0; it < 2; it++) {
            int m = 64 * it + l64;
            int q0 = 4 * m;
            if (q0 >= C1_SPAN) break;
            float p0v[6], p1v[6], p2v[6], p3v[6], p4v[6];
            {
                const float* r0 = sm + SM_INP + 0 * INP_ROW + q0;
                const float* r1 = sm + SM_INP + 1 * INP_ROW + q0;
                const float* r2 = sm + SM_INP + 2 * INP_ROW + q0;
                const float* r3 = sm + SM_INP + 3 * INP_ROW + q0;
                const float* r4 = sm + SM_INP + 4 * INP_ROW + q0;
                float4 v;
                v = *(const float4*)r0; p0v[0]=v.x; p0v[1]=v.y; p0v[2]=v.z; p0v[3]=v.w; p0v[4]=r0[4]; p0v[5]=r0[5];
                v = *(const float4*)r1; p1v[0]=v.x; p1v[1]=v.y; p1v[2]=v.z; p1v[3]=v.w; p1v[4]=r1[4];
                v = *(const float4*)r2; p2v[0]=v.x; p2v[1]=v.y; p2v[2]=v.z; p2v[3]=v.w; p2v[4]=r2[4];
                v = *(const float4*)r3; p3v[0]=v.x; p3v[1]=v.y; p3v[2]=v.z; p3v[3]=v.w; p3v[4]=r3[4];
                v = *(const float4*)r4; p4v[0]=v.x; p4v[1]=v.y; p4v[2]=v.z; p4v[3]=v.w; p4v[4]=r4[4];
            }
            #pragma unroll
            for (int i = 0; i < 4; i++) {
                int q = q0 + i;
                if (q >= C1_SPAN) break;
                ULL acc = bpair;
                fma2(acc, wreg[0],  pk2(p0v[i],   p0v[i]));
                fma2(acc, wreg[1],  pk2(p1v[i],   p1v[i]));
                fma2(acc, wreg[2],  pk2(p2v[i],   p2v[i]));
                fma2(acc, wreg[3],  pk2(p3v[i],   p3v[i]));
                fma2(acc, wreg[4],  pk2(p4v[i],   p4v[i]));
                fma2(acc, wreg[5],  pk2(p0v[i+1], p0v[i+1]));
                fma2(acc, wreg[6],  pk2(p1v[i+1], p1v[i+1]));
                fma2(acc, wreg[7],  pk2(p2v[i+1], p2v[i+1]));
                fma2(acc, wreg[8],  pk2(p3v[i+1], p3v[i+1]));
                fma2(acc, wreg[9],  pk2(p4v[i+1], p4v[i+1]));
                fma2(acc, wreg[10], pk2(p0v[i+2], p0v[i+2]));
                float r0, r1; upk2(acc, r0, r1);
                bool ok = ((unsigned)(q0g + q) < L1_LEN);
                r0 = ok ? fmaxf(r0, 0.f) : 0.f;
                r1 = ok ? fmaxf(r1, 0.f) : 0.f;
                int ph = q % 5, j = q / 5;
                sm[SM_C1P + (ph * 8 + 2*grp)     * C1_ROW + j] = r0;
                sm[SM_C1P + (ph * 8 + 2*grp + 1) * C1_ROW + j] = r1;
            }
        }
    }
    __syncthreads();

    // conv2
    {
        const int pr = tid >> 5;
        const int m  = tid & 31;
        if (m < 25) {
            const int p0 = 4 * m;
            ULL acc[4];
            const ULL bpair = pk2(sm[SM_B2 + 2*pr], sm[SM_B2 + 2*pr + 1]);
            #pragma unroll
            for (int i = 0; i < 4; i++) acc[i] = bpair;
            const ULL* wbase = (const ULL*)(sm + SM_W2) + pr * 56;
            #pragma unroll
            for (int ic = 0; ic < 8; ic++) {
                ULL wreg[7];
                #pragma unroll
                for (int k = 0; k < 7; k++) wreg[k] = wbase[ic * 7 + k];
                float p0v[5], p1v[5], p2v[4], p3v[4], p4v[4];
                {
                    const float* r0 = sm + SM_C1P + (0 * 8 + ic) * C1_ROW + p0;
                    const float* r1 = sm + SM_C1P + (1 * 8 + ic) * C1_ROW + p0;
                    const float* r2 = sm + SM_C1P + (2 * 8 + ic) * C1_ROW + p0;
                    const float* r3 = sm + SM_C1P + (3 * 8 + ic) * C1_ROW + p0;
                    const float* r4 = sm + SM_C1P + (4 * 8 + ic) * C1_ROW + p0;
                    float4 v;
                    v = *(const float4*)r0; p0v[0]=v.x; p0v[1]=v.y; p0v[2]=v.z; p0v[3]=v.w; p0v[4]=r0[4];
                    v = *(const float4*)r1; p1v[0]=v.x; p1v[1]=v.y; p1v[2]=v.z; p1v[3]=v.w; p1v[4]=r1[4];
                    v = *(const float4*)r2; p2v[0]=v.x; p2v[1]=v.y; p2v[2]=v.z; p2v[3]=v.w;
                    v = *(const float4*)r3; p3v[0]=v.x; p3v[1]=v.y; p3v[2]=v.z; p3v[3]=v.w;
                    v = *(const float4*)r4; p4v[0]=v.x; p4v[1]=v.y; p4v[2]=v.z; p4v[3]=v.w;
                }
                #pragma unroll
                for (int i = 0; i < 4; i++) {
                    fma2(acc[i], wreg[0], pk2(p0v[i],   p0v[i]));
                    fma2(acc[i], wreg[1], pk2(p1v[i],   p1v[i]));
                    fma2(acc[i], wreg[2], pk2(p2v[i],   p2v[i]));
                    fma2(acc[i], wreg[3], pk2(p3v[i],   p3v[i]));
                    fma2(acc[i], wreg[4], pk2(p4v[i],   p4v[i]));
                    fma2(acc[i], wreg[5], pk2(p0v[i+1], p0v[i+1]));
                    fma2(acc[i], wreg[6], pk2(p1v[i+1], p1v[i+1]));
                }
            }
            const int p0g = 5 * t0 - 2;
            #pragma unroll
            for (int i = 0; i < 4; i++) {
                int p = p0 + i;
                float r0, r1; upk2(acc[i], r0, r1);
                bool ok = ((unsigned)(p0g + p) < L2_LEN);
                r0 = ok ? fmaxf(r0, 0.f) : 0.f;
                r1 = ok ? fmaxf(r1, 0.f) : 0.f;
                int ph = p % 5, j = p / 5;
                sm[SM_C2P + (ph * 16 + 2*pr)     * C2_ROW + j] = r0;
                sm[SM_C2P + (ph * 16 + 2*pr + 1) * C2_ROW + j] = r1;
            }
        }
    }
    __syncthreads();

    // conv3 -> x tile into smem (c1 region is dead; reuse as xbuf[20][32])
    if (tid < 80) {
        const int pr  = tid / 5;
        const int tl0 = (tid % 5) * 4;
        ULL acc[4];
        const ULL bpair = pk2(sm[SM_B3 + 2*pr], sm[SM_B3 + 2*pr + 1]);
        #pragma unroll
        for (int i = 0; i < 4; i++) acc[i] = bpair;
        const ULL* wbase = (const ULL*)(sm + SM_W3) + pr * 80;
        #pragma unroll
        for (int ic = 0; ic < 16; ic++) {
            ULL wreg[5];
            #pragma unroll
            for (int k = 0; k < 5; k++) wreg[k] = wbase[ic * 5 + k];
            float4 P0 = *(const float4*)(sm + SM_C2P + (0 * 16 + ic) * C2_ROW + tl0);
            float4 P1 = *(const float4*)(sm + SM_C2P + (1 * 16 + ic) * C2_ROW + tl0);
            float4 P2 = *(const float4*)(sm + SM_C2P + (2 * 16 + ic) * C2_ROW + tl0);
            float4 P3 = *(const float4*)(sm + SM_C2P + (3 * 16 + ic) * C2_ROW + tl0);
            float4 P4 = *(const float4*)(sm + SM_C2P + (4 * 16 + ic) * C2_ROW + tl0);
            const float* a0 = (const float*)&P0;
            const float* a1 = (const float*)&P1;
            const float* a2 = (const float*)&P2;
            const float* a3 = (const float*)&P3;
            const float* a4 = (const float*)&P4;
            #pragma unroll
            for (int i = 0; i < 4; i++) {
                fma2(acc[i], wreg[0], pk2(a0[i], a0[i]));
                fma2(acc[i], wreg[1], pk2(a1[i], a1[i]));
                fma2(acc[i], wreg[2], pk2(a2[i], a2[i]));
                fma2(acc[i], wreg[3], pk2(a3[i], a3[i]));
                fma2(acc[i], wreg[4], pk2(a4[i], a4[i]));
            }
        }
        float* xb = sm + SM_C1P;   // xbuf[20][32]
        #pragma unroll
        for (int i = 0; i < 4; i++) {
            float r0, r1; upk2(acc[i], r0, r1);
            xb[(tl0 + i) * 32 + 2*pr]     = fmaxf(r0, 0.f);
            xb[(tl0 + i) * 32 + 2*pr + 1] = fmaxf(r1, 0.f);
        }
    }
    __syncthreads();

    // ---- gi epilogue: 384 (dir,row) pairs over 256 threads ----
    {
        const float* xb = sm + SM_C1P;
        for (int p = tid; p < 384; p += 256) {
            const int dir = p / 192, row = p - dir * 192;
            const float* wsrc = dir ? wih_b : wih_f;
            const float* bsrc = dir ? bih_b : bih_f;
            ULL wreg[16];
            {
                const ULL* wp = (const ULL*)(wsrc + row * 32);
                #pragma unroll
                for (int i = 0; i < 16; i++) wreg[i] = wp[i];
            }
            const float b = bsrc[row];
            float* gout = g_gi + (size_t)(dir * 256 + c) * SEQ_STRIDE + row;
            #pragma unroll 4
            for (int k = 0; k < TILE; k++) {
                const ulonglong2* xp = (const ulonglong2*)(xb + k * 32);
                ULL a0 = pk2(b, 0.f), a1 = pk2(0.f, 0.f);
                #pragma unroll
                for (int i = 0; i < 8; i++) {
                    ulonglong2 u = xp[i];
                    fma2(a0, wreg[2*i],   u.x);
                    fma2(a1, wreg[2*i+1], u.y);
                }
                float lo, hi, v;
                upk2(a0, lo, hi); v  = lo + hi;
                upk2(a1, lo, hi); v += lo + hi;
                int sg = dir ? (L3_LEN - 1 - (t0 + k)) : (t0 + k);
                gout[(size_t)sg * 192] = v;
            }
        }
    }
}

// =====================================================================
// Kernel: GRU recurrence (measured-best k_gru2, unchanged)
// =====================================================================
__global__ __launch_bounds__(128, 3) void k_gru2(
    const float* __restrict__ whh_f, const float* __restrict__ bhh_f,
    const float* __restrict__ whh_b, const float* __restrict__ bhh_b)
{
    const int blk = blockIdx.x;       // 0..255
    const int dir = blk & 1;
    const int cp  = blk >> 1;
    const int c0 = 2 * cp, c1 = 2 * cp + 1;
    const float* whh = dir ? whh_b : whh_f;
    const float* bhh = dir ? bhh_b : bhh_f;
    const int t = threadIdx.x;
    const int j = t >> 1, half = t & 1;

    ULL wr_[16], wz_[16], wn_[16];
    {
        const ULL* pr = (const ULL*)(whh + (j      ) * 64 + half * 32);
        const ULL* pz = (const ULL*)(whh + (j +  64) * 64 + half * 32);
        const ULL* pn = (const ULL*)(whh + (j + 128) * 64 + half * 32);
        #pragma unroll
        for (int i = 0; i < 16; i++) { wr_[i] = pr[i]; wz_[i] = pz[i]; wn_[i] = pn[i]; }
    }
    const float br = half ? 0.f : bhh[j];
    const float bz = half ? 0.f : bhh[j + 64];
    const float bn = half ? 0.f : bhh[j + 128];

    const float* giA = g_gi + (size_t)(dir * 256 + c0) * SEQ_STRIDE;
    const float* giB = g_gi + (size_t)(dir * 256 + c1) * SEQ_STRIDE;

    __shared__ __align__(16) float hs[2][2][64];          // [buf][seq][j]
    __shared__ __align__(16) float gsm[2][GCH][2][192];   // [buf][sl][seq][row]

    if (t < 64) { hs[0][0][t] = 0.f; hs[0][1][t] = 0.f; }

    #pragma unroll
    for (int k = 0; k < 3; k++) {
        int fi = t + k * 128;
        int sl = fi / 96, rem = fi % 96;
        int seq = rem / 48, r4 = rem % 48;
        const float* src = (seq ? giB : giA) + (size_t)sl * 192 + r4 * 4;
        *(float4*)&gsm[0][sl][seq][r4 * 4] = *(const float4*)src;
    }
    float hA = 0.f, hB = 0.f;
    __syncthreads();

    float4 pf[3];

    #pragma unroll 1
    for (int s = 0; s < L3_LEN; s++) {
        const int sl  = s & (GCH - 1);
        const int chk = s >> 2;
        const int buf = chk & 1;

        if (sl == 0 && chk + 1 < L3_LEN / GCH) {
            int step0 = (chk + 1) * GCH;
            #pragma unroll
            for (int k = 0; k < 3; k++) {
                int fi = t + k * 128;
                int psl = fi / 96, rem = fi % 96;
                int seq = rem / 48, r4 = rem % 48;
                const float* src = (seq ? giB : giA) + (size_t)(step0 + psl) * 192 + r4 * 4;
                pf[k] = *(const float4*)src;
            }
        }

        const ulonglong2* hpA = (const ulonglong2*)hs[s & 1][0] + half * 8;
        const ulonglong2* hpB = (const ulonglong2*)hs[s & 1][1] + half * 8;
        ULL arA = pk2(br, 0.f), azA = pk2(bz, 0.f), anA = pk2(bn, 0.f);
        ULL arA1 = pk2(0.f,0.f), azA1 = pk2(0.f,0.f), anA1 = pk2(0.f,0.f);
        ULL arB = pk2(br, 0.f), azB = pk2(bz, 0.f), anB = pk2(bn, 0.f);
        ULL arB1 = pk2(0.f,0.f), azB1 = pk2(0.f,0.f), anB1 = pk2(0.f,0.f);
        #pragma unroll
        for (int i = 0; i < 8; i++) {
            ulonglong2 uA = hpA[i];
            fma2(arA, wr_[2*i], uA.x);  fma2(arA1, wr_[2*i+1], uA.y);
            fma2(azA, wz_[2*i], uA.x);  fma2(azA1, wz_[2*i+1], uA.y);
            fma2(anA, wn_[2*i], uA.x);  fma2(anA1, wn_[2*i+1], uA.y);
            ulonglong2 uB = hpB[i];
            fma2(arB, wr_[2*i], uB.x);  fma2(arB1, wr_[2*i+1], uB.y);
            fma2(azB, wz_[2*i], uB.x);  fma2(azB1, wz_[2*i+1], uB.y);
            fma2(anB, wn_[2*i], uB.x);  fma2(anB1, wn_[2*i+1], uB.y);
        }
        float lo, hi;
        float ghrA, ghzA, ghnA, ghrB, ghzB, ghnB;
        upk2(arA, lo, hi);  ghrA  = lo + hi;  upk2(arA1, lo, hi); ghrA += lo + hi;
        upk2(azA, lo, hi);  ghzA  = lo + hi;  upk2(azA1, lo, hi); ghzA += lo + hi;
        upk2(anA, lo, hi);  ghnA  = lo + hi;  upk2(anA1, lo, hi); ghnA += lo + hi;
        upk2(arB, lo, hi);  ghrB  = lo + hi;  upk2(arB1, lo, hi); ghrB += lo + hi;
        upk2(azB, lo, hi);  ghzB  = lo + hi;  upk2(azB1, lo, hi); ghzB += lo + hi;
        upk2(anB, lo, hi);  ghnB  = lo + hi;  upk2(anB1, lo, hi); ghnB += lo + hi;

        ghrA += __shfl_xor_sync(0xffffffffu, ghrA, 1);
        ghzA += __shfl_xor_sync(0xffffffffu, ghzA, 1);
        ghnA += __shfl_xor_sync(0xffffffffu, ghnA, 1);
        ghrB += __shfl_xor_sync(0xffffffffu, ghrB, 1);
        ghzB += __shfl_xor_sync(0xffffffffu, ghzB, 1);
        ghnB += __shfl_xor_sync(0xffffffffu, ghnB, 1);

        if (half == 0) {
            const float* gA = gsm[buf][sl][0];
            const float* gB = gsm[buf][sl][1];
            float rA = sigmoid_f(gA[j] + ghrA);
            float zA = sigmoid_f(gA[j + 64] + ghzA);
            float nA = tanh_f(fmaf(rA, ghnA, gA[j + 128]));
            hA = fmaf(zA, hA - nA, nA);
            hs[(s + 1) & 1][0][j] = hA;
            float rB = sigmoid_f(gB[j] + ghrB);
            float zB = sigmoid_f(gB[j + 64] + ghzB);
            float nB = tanh_f(fmaf(rB, ghnB, gB[j + 128]));
            hB = fmaf(zB, hB - nB, nB);
            hs[(s + 1) & 1][1][j] = hB;
        }
        if (sl == GCH - 1 && chk + 1 < L3_LEN / GCH) {
            #pragma unroll
            for (int k = 0; k < 3; k++) {
                int fi = t + k * 128;
                int psl = fi / 96, rem = fi % 96;
                int seq = rem / 48, r4 = rem % 48;
                *(float4*)&gsm[buf ^ 1][psl][seq][r4 * 4] = pf[k];
            }
        }
        __syncthreads();
    }
    if (half == 0) {
        g_hn[c0 * 128 + dir * 64 + j] = hA;
        g_hn[c1 * 128 + dir * 64 + j] = hB;
    }
}

// =====================================================================
// per-row normalize
// =====================================================================
__global__ void k_norm()
{
    const int i = blockIdx.x, t = threadIdx.x;
    float v = g_hn[i * 128 + t];
    __shared__ float red[4], red2[4];
    float s = v;
    #pragma unroll
    for (int o = 16; o; o >>= 1) s += __shfl_xor_sync(0xffffffffu, s, o);
    if ((t & 31) == 0) red[t >> 5] = s;
    __syncthreads();
    float mean = (red[0] + red[1] + red[2] + red[3]) * (1.f / 128.f);
    float d = v - mean;
    float s2 = d * d;
    #pragma unroll
    for (int o = 16; o; o >>= 1) s2 += __shfl_xor_sync(0xffffffffu, s2, o);
    if ((t & 31) == 0) red2[t >> 5] = s2;
    __syncthreads();
    float var = (red2[0] + red2[1] + red2[2] + red2[3]) * (1.f / 127.f);
    g_xnT[t * N_CH + i] = d / (sqrtf(var) + 1e-6f);
}

// =====================================================================
// adjacency row + degree + M1
// =====================================================================
__global__ void k_adj(const float* __restrict__ g1w)
{
    const int i = blockIdx.x, t = threadIdx.x;
    __shared__ float xi[128], hi[128];
    __shared__ float degred[8];
    if (t < 128) { xi[t] = g_xnT[t * N_CH + i]; hi[t] = g_hn[i * 128 + t]; }
    __syncthreads();

    float acc = 0.f;
    #pragma unroll 4
    for (int k = 0; k < 128; k++) acc = fmaf(xi[k], g_xnT[k * N_CH + t], acc);
    acc *= (1.f / 128.f);
    float a = (fabsf(acc) > 0.7f) ? 1.f : 0.f;
    g_A[i * N_CH + t] = a;

    float s = a;
    #pragma unroll
    for (int o = 16; o; o >>= 1) s += __shfl_xor_sync(0xffffffffu, s, o);
    if ((t & 31) == 0) degred[t >> 5] = s;
    __syncthreads();
    if (t == 0) {
        float deg = 0.f;
        #pragma unroll
        for (int w = 0; w < 8; w++) deg += degred[w];
        g_dinv[i] = rsqrtf(fmaxf(deg, 1e-12f));
    }
    if (t < 32) {
        float m = 0.f;
        const float* wr = g1w + t * 128;
        #pragma unroll 4
        for (int k = 0; k < 128; k++) m = fmaf(hi[k], wr[k], m);
        g_M1[i * 32 + t] = m;
    }
}

// =====================================================================
__global__ void k_gcn1(const float* __restrict__ b1, const float* __restrict__ w2)
{
    const int i = blockIdx.x, t = threadIdx.x;
    const float di = g_dinv[i];
    float acc = 0.f;
    for (int j = 0; j < N_CH; j++) {
        float aij = g_A[i * N_CH + j];
        if (aij != 0.f) acc = fmaf(g_dinv[j], g_M1[j * 32 + t], acc);
    }
    float h1 = fmaxf(fmaf(di, acc, b1[t]), 0.f);
    __shared__ float h1s[32];
    h1s[t] = h1;
    __syncthreads();
    float m2 = 0.f;
    const float* wr = w2 + t * 32;
    #pragma unroll
    for (int o = 0; o < 32; o++) m2 = fmaf(h1s[o], wr[o], m2);
    g_M2[i * 32 + t] = m2;
}

__global__ void k_gcn2(const float* __restrict__ b2)
{
    const int i = blockIdx.x, t = threadIdx.x;
    const float di = g_dinv[i];
    float acc = 0.f;
    for (int j = 0; j < N_CH; j++) {
        float aij = g_A[i * N_CH + j];
        if (aij != 0.f) acc = fmaf(g_dinv[j], g_M2[j * 32 + t], acc);
    }
    g_h2[i * 32 + t] = fmaxf(fmaf(di, acc, b2[t]), 0.f);
}

__global__ void k_final(const float* __restrict__ cw, const float* __restrict__ cb,
                        float* __restrict__ out)
{
    const int t = threadIdx.x;
    float acc = 0.f;
    for (int i = 0; i < N_CH; i++) acc += g_h2[i * 32 + t];
    __shared__ float es[32];
    es[t] = acc * (1.f / 256.f);
    __syncthreads();
    if (t < 2) {
        float o = cb[t];
        #pragma unroll
        for (int k = 0; k < 32; k++) o = fmaf(es[k], cw[t * 32 + k], o);
        out[t] = o;
    }
}

// =====================================================================
extern "C" void kernel_launch(void* const* d_in, const int* in_sizes, int n_in,
                              void* d_out, int out_size)
{
    const float* data    = (const float*)d_in[0];
    const float* conv1_w = (const float*)d_in[1];
    const float* conv1_b = (const float*)d_in[2];
    const float* conv2_w = (const float*)d_in[3];
    const float* conv2_b = (const float*)d_in[4];
    const float* conv3_w = (const float*)d_in[5];
    const float* conv3_b = (const float*)d_in[6];
    const float* wih_f   = (const float*)d_in[7];
    const float* whh_f   = (const float*)d_in[8];
    const float* bih_f   = (const float*)d_in[9];
    const float* bhh_f   = (const float*)d_in[10];
    const float* wih_b   = (const float*)d_in[11];
    const float* whh_b   = (const float*)d_in[12];
    const float* bih_b   = (const float*)d_in[13];
    const float* bhh_b   = (const float*)d_in[14];
    const float* gcn1_w  = (const float*)d_in[15];
    const float* gcn1_b  = (const float*)d_in[16];
    const float* gcn2_w  = (const float*)d_in[17];
    const float* gcn2_b  = (const float*)d_in[18];
    const float* cls_w   = (const float*)d_in[19];
    const float* cls_b   = (const float*)d_in[20];

    // launch order: profiled slot #4 = fused conv+gi
    k_prep1<<<1, 64>>>(conv1_w);
    k_prep2<<<1, 256>>>(conv2_w);
    k_prep3<<<1, 256>>>(conv3_w);
    k_conv_fused<<<N_CH * NTILE, 256>>>(data, conv1_b, conv2_b, conv3_b,
                                        wih_f, bih_f, wih_b, bih_b);
    k_gru2<<<256, 128>>>(whh_f, bhh_f, whh_b, bhh_b);
    k_norm<<<N_CH, 128>>>();
    k_adj<<<N_CH, 256>>>(gcn1_w);
    k_gcn1<<<N_CH, 32>>>(gcn1_b, gcn2_w);
    k_gcn2<<<N_CH, 32>>>(gcn2_b);
    k_final<<<1, 32>>>(cls_w, cls_b, (float*)d_out);
}

// round 15
// speedup vs baseline: 1.2006x; 1.2006x over previous
#include <cuda_runtime.h>
#include <math.h>

// ---------------- problem constants ----------------
#define N_CH   256
#define T_IN   100000
#define L1_LEN 20000
#define L2_LEN 4000
#define L3_LEN 800
#define CNN_OUT 32
#define GRU_H   64

// conv fused tiling
#define TILE   20
#define NTILE  (L3_LEN / TILE)
#define C2_SPAN 100
#define C1_SPAN 502

#define INP_ROW 508
#define C1_ROW  104
#define C2_ROW  20

// interleaved conv-weight table
#define W1I_OFF 0
#define W2I_OFF 88
#define W3I_OFF 984
#define WCONV_TOT 3544

// GRU gi chunking
#define GCH 4                      // steps per staged chunk (recurrence)
#define SEQ_STRIDE (800 * 192)     // floats per sequence in g_gi
#define GI_SPB 200                 // steps per gi block
#define GI_SCH 25                  // steps staged per smem sub-chunk

typedef unsigned long long ULL;

// ---------------- f32x2 helpers ----------------
__device__ __forceinline__ ULL pk2(float a, float b) {
    ULL r; asm("mov.b64 %0, {%1, %2};" : "=l"(r) : "f"(a), "f"(b)); return r;
}
__device__ __forceinline__ void upk2(ULL v, float &a, float &b) {
    asm("mov.b64 {%0, %1}, %2;" : "=f"(a), "=f"(b) : "l"(v));
}
__device__ __forceinline__ void fma2(ULL &d, ULL a, ULL b) {
    asm("fma.rn.f32x2 %0, %1, %2, %0;" : "+l"(d) : "l"(a), "l"(b));
}

__device__ __forceinline__ float sigmoid_f(float x) {
    return __fdividef(1.f, 1.f + __expf(-x));
}
__device__ __forceinline__ float tanh_f(float x) {
    return 1.f - __fdividef(2.f, __expf(2.f * x) + 1.f);
}

// ---------------- scratch (static device, no allocation) ----------------
__device__ __align__(16) float g_wconv[WCONV_TOT];
__device__ __align__(16) float g_x3[N_CH * L3_LEN * CNN_OUT];   // conv3 out [c][t][f]
__device__ __align__(16) float g_gi[512 * SEQ_STRIDE];          // gi[seq][step][row]
__device__ float g_hn[N_CH * 128];
__device__ float g_xnT[128 * N_CH];
__device__ float g_A[N_CH * N_CH];
__device__ float g_dinv[N_CH];
__device__ float g_M1[N_CH * 32];
__device__ float g_M2[N_CH * 32];
__device__ float g_h2[N_CH * 32];

// =====================================================================
// Prep kernels: interleave conv weights (2 kernels so ncu slot #4 = k_gi)
// =====================================================================
__global__ void k_prep_a(const float* __restrict__ w1, const float* __restrict__ w2)
{
    const int tid = threadIdx.x;
    if (tid < 44) {
        int pr = tid / 11, k = tid - pr * 11;
        g_wconv[W1I_OFF + 2*tid]     = w1[(2*pr)   * 11 + k];
        g_wconv[W1I_OFF + 2*tid + 1] = w1[(2*pr+1) * 11 + k];
    }
    for (int i = tid; i < 448; i += 256) {
        int k = i % 7, ic = (i / 7) % 8, pr = i / 56;
        g_wconv[W2I_OFF + 2*i]     = w2[((2*pr)   * 8 + ic) * 7 + k];
        g_wconv[W2I_OFF + 2*i + 1] = w2[((2*pr+1) * 8 + ic) * 7 + k];
    }
}
__global__ void k_prep_b(const float* __restrict__ w3)
{
    const int tid = threadIdx.x;
    for (int i = tid; i < 1280; i += 256) {
        int k = i % 5, ic = (i / 5) % 16, pr = i / 80;
        g_wconv[W3I_OFF + 2*i]     = w3[((2*pr)   * 16 + ic) * 5 + k];
        g_wconv[W3I_OFF + 2*i + 1] = w3[((2*pr+1) * 16 + ic) * 5 + k];
    }
}

// =====================================================================
// Kernel: fused conv1+conv2+conv3 (R13 measured version, writes g_x3)
// =====================================================================
#define SM_INP  0
#define SM_C1P  (SM_INP + 5*INP_ROW)
#define SM_C2P  (SM_C1P + 5*8*C1_ROW)
#define SM_W1   (SM_C2P + 5*16*C2_ROW)
#define SM_W2   (SM_W1 + 88)
#define SM_W3   (SM_W2 + 896)
#define SM_B1   (SM_W3 + 2560)
#define SM_B2   (SM_B1 + 8)
#define SM_B3   (SM_B2 + 16)
#define SM_TOT  (SM_B3 + 32)

__global__ __launch_bounds__(256) void k_conv_fused(
    const float* __restrict__ data,
    const float* __restrict__ b1,
    const float* __restrict__ b2,
    const float* __restrict__ b3)
{
    __shared__ __align__(16) float sm[SM_TOT];

    const int tid = threadIdx.x;
    const int c   = blockIdx.x / NTILE;
    const int t0  = (blockIdx.x % NTILE) * TILE;

    {
        const float4* src = (const float4*)g_wconv;
        float4* dst = (float4*)(sm + SM_W1);
        for (int i = tid; i < WCONV_TOT / 4; i += 256) dst[i] = src[i];
    }
    if (tid < 8)  sm[SM_B1 + tid] = b1[tid];
    if (tid < 16) sm[SM_B2 + tid] = b2[tid];
    if (tid < 32) sm[SM_B3 + tid] = b3[tid];

    {
        const float* dch = data + (size_t)c * T_IN;
        const int base = 125 * t0 - 70;
        for (int i = tid; i < 5 * INP_ROW; i += 256) {
            int g = base + i;
            float v = (g >= 0 && g < T_IN) ? dch[g] : 0.f;
            sm[SM_INP + (i % 5) * INP_ROW + (i / 5)] = v;
        }
    }
    __syncthreads();

    // conv1
    {
        const int grp = tid >> 6;
        const int l64 = tid & 63;
        ULL wreg[11];
        {
            const ULL* wp = (const ULL*)(sm + SM_W1) + grp * 11;
            #pragma unroll
            for (int k = 0; k < 11; k++) wreg[k] = wp[k];
        }
        const ULL bpair = pk2(sm[SM_B1 + 2*grp], sm[SM_B1 + 2*grp + 1]);
        const int q0g = 25 * t0 - 13;

        #pragma unroll
        for (int it = 0; it < 2; it++) {
            int m = 64 * it + l64;
            int q0 = 4 * m;
            if (q0 >= C1_SPAN) break;
            float p0v[6], p1v[6], p2v[6], p3v[6], p4v[6];
            {
                const float* r0 = sm + SM_INP + 0 * INP_ROW + q0;
                const float* r1 = sm + SM_INP + 1 * INP_ROW + q0;
                const float* r2 = sm + SM_INP + 2 * INP_ROW + q0;
                const float* r3 = sm + SM_INP + 3 * INP_ROW + q0;
                const float* r4 = sm + SM_INP + 4 * INP_ROW + q0;
                float4 v;
                v = *(const float4*)r0; p0v[0]=v.x; p0v[1]=v.y; p0v[2]=v.z; p0v[3]=v.w; p0v[4]=r0[4]; p0v[5]=r0[5];
                v = *(const float4*)r1; p1v[0]=v.x; p1v[1]=v.y; p1v[2]=v.z; p1v[3]=v.w; p1v[4]=r1[4];
                v = *(const float4*)r2; p2v[0]=v.x; p2v[1]=v.y; p2v[2]=v.z; p2v[3]=v.w; p2v[4]=r2[4];
                v = *(const float4*)r3; p3v[0]=v.x; p3v[1]=v.y; p3v[2]=v.z; p3v[3]=v.w; p3v[4]=r3[4];
                v = *(const float4*)r4; p4v[0]=v.x; p4v[1]=v.y; p4v[2]=v.z; p4v[3]=v.w; p4v[4]=r4[4];
            }
            #pragma unroll
            for (int i = 0; i < 4; i++) {
                int q = q0 + i;
                if (q >= C1_SPAN) break;
                ULL acc = bpair;
                fma2(acc, wreg[0],  pk2(p0v[i],   p0v[i]));
                fma2(acc, wreg[1],  pk2(p1v[i],   p1v[i]));
                fma2(acc, wreg[2],  pk2(p2v[i],   p2v[i]));
                fma2(acc, wreg[3],  pk2(p3v[i],   p3v[i]));
                fma2(acc, wreg[4],  pk2(p4v[i],   p4v[i]));
                fma2(acc, wreg[5],  pk2(p0v[i+1], p0v[i+1]));
                fma2(acc, wreg[6],  pk2(p1v[i+1], p1v[i+1]));
                fma2(acc, wreg[7],  pk2(p2v[i+1], p2v[i+1]));
                fma2(acc, wreg[8],  pk2(p3v[i+1], p3v[i+1]));
                fma2(acc, wreg[9],  pk2(p4v[i+1], p4v[i+1]));
                fma2(acc, wreg[10], pk2(p0v[i+2], p0v[i+2]));
                float r0, r1; upk2(acc, r0, r1);
                bool ok = ((unsigned)(q0g + q) < L1_LEN);
                r0 = ok ? fmaxf(r0, 0.f) : 0.f;
                r1 = ok ? fmaxf(r1, 0.f) : 0.f;
                int ph = q % 5, j = q / 5;
                sm[SM_C1P + (ph * 8 + 2*grp)     * C1_ROW + j] = r0;
                sm[SM_C1P + (ph * 8 + 2*grp + 1) * C1_ROW + j] = r1;
            }
        }
    }
    __syncthreads();

    // conv2
    {
        const int pr = tid >> 5;
        const int m  = tid & 31;
        if (m < 25) {
            const int p0 = 4 * m;
            ULL acc[4];
            const ULL bpair = pk2(sm[SM_B2 + 2*pr], sm[SM_B2 + 2*pr + 1]);
            #pragma unroll
            for (int i = 0; i < 4; i++) acc[i] = bpair;
            const ULL* wbase = (const ULL*)(sm + SM_W2) + pr * 56;
            #pragma unroll
            for (int ic = 0; ic < 8; ic++) {
                ULL wreg[7];
                #pragma unroll
                for (int k = 0; k < 7; k++) wreg[k] = wbase[ic * 7 + k];
                float p0v[5], p1v[5], p2v[4], p3v[4], p4v[4];
                {
                    const float* r0 = sm + SM_C1P + (0 * 8 + ic) * C1_ROW + p0;
                    const float* r1 = sm + SM_C1P + (1 * 8 + ic) * C1_ROW + p0;
                    const float* r2 = sm + SM_C1P + (2 * 8 + ic) * C1_ROW + p0;
                    const float* r3 = sm + SM_C1P + (3 * 8 + ic) * C1_ROW + p0;
                    const float* r4 = sm + SM_C1P + (4 * 8 + ic) * C1_ROW + p0;
                    float4 v;
                    v = *(const float4*)r0; p0v[0]=v.x; p0v[1]=v.y; p0v[2]=v.z; p0v[3]=v.w; p0v[4]=r0[4];
                    v = *(const float4*)r1; p1v[0]=v.x; p1v[1]=v.y; p1v[2]=v.z; p1v[3]=v.w; p1v[4]=r1[4];
                    v = *(const float4*)r2; p2v[0]=v.x; p2v[1]=v.y; p2v[2]=v.z; p2v[3]=v.w;
                    v = *(const float4*)r3; p3v[0]=v.x; p3v[1]=v.y; p3v[2]=v.z; p3v[3]=v.w;
                    v = *(const float4*)r4; p4v[0]=v.x; p4v[1]=v.y; p4v[2]=v.z; p4v[3]=v.w;
                }
                #pragma unroll
                for (int i = 0; i < 4; i++) {
                    fma2(acc[i], wreg[0], pk2(p0v[i],   p0v[i]));
                    fma2(acc[i], wreg[1], pk2(p1v[i],   p1v[i]));
                    fma2(acc[i], wreg[2], pk2(p2v[i],   p2v[i]));
                    fma2(acc[i], wreg[3], pk2(p3v[i],   p3v[i]));
                    fma2(acc[i], wreg[4], pk2(p4v[i],   p4v[i]));
                    fma2(acc[i], wreg[5], pk2(p0v[i+1], p0v[i+1]));
                    fma2(acc[i], wreg[6], pk2(p1v[i+1], p1v[i+1]));
                }
            }
            const int p0g = 5 * t0 - 2;
            #pragma unroll
            for (int i = 0; i < 4; i++) {
                int p = p0 + i;
                float r0, r1; upk2(acc[i], r0, r1);
                bool ok = ((unsigned)(p0g + p) < L2_LEN);
                r0 = ok ? fmaxf(r0, 0.f) : 0.f;
                r1 = ok ? fmaxf(r1, 0.f) : 0.f;
                int ph = p % 5, j = p / 5;
                sm[SM_C2P + (ph * 16 + 2*pr)     * C2_ROW + j] = r0;
                sm[SM_C2P + (ph * 16 + 2*pr + 1) * C2_ROW + j] = r1;
            }
        }
    }
    __syncthreads();

    // conv3
    if (tid < 80) {
        const int pr  = tid / 5;
        const int tl0 = (tid % 5) * 4;
        ULL acc[4];
        const ULL bpair = pk2(sm[SM_B3 + 2*pr], sm[SM_B3 + 2*pr + 1]);
        #pragma unroll
        for (int i = 0; i < 4; i++) acc[i] = bpair;
        const ULL* wbase = (const ULL*)(sm + SM_W3) + pr * 80;
        #pragma unroll
        for (int ic = 0; ic < 16; ic++) {
            ULL wreg[5];
            #pragma unroll
            for (int k = 0; k < 5; k++) wreg[k] = wbase[ic * 5 + k];
            float4 P0 = *(const float4*)(sm + SM_C2P + (0 * 16 + ic) * C2_ROW + tl0);
            float4 P1 = *(const float4*)(sm + SM_C2P + (1 * 16 + ic) * C2_ROW + tl0);
            float4 P2 = *(const float4*)(sm + SM_C2P + (2 * 16 + ic) * C2_ROW + tl0);
            float4 P3 = *(const float4*)(sm + SM_C2P + (3 * 16 + ic) * C2_ROW + tl0);
            float4 P4 = *(const float4*)(sm + SM_C2P + (4 * 16 + ic) * C2_ROW + tl0);
            const float* a0 = (const float*)&P0;
            const float* a1 = (const float*)&P1;
            const float* a2 = (const float*)&P2;
            const float* a3 = (const float*)&P3;
            const float* a4 = (const float*)&P4;
            #pragma unroll
            for (int i = 0; i < 4; i++) {
                fma2(acc[i], wreg[0], pk2(a0[i], a0[i]));
                fma2(acc[i], wreg[1], pk2(a1[i], a1[i]));
                fma2(acc[i], wreg[2], pk2(a2[i], a2[i]));
                fma2(acc[i], wreg[3], pk2(a3[i], a3[i]));
                fma2(acc[i], wreg[4], pk2(a4[i], a4[i]));
            }
        }
        #pragma unroll
        for (int i = 0; i < 4; i++) {
            float r0, r1; upk2(acc[i], r0, r1);
            r0 = fmaxf(r0, 0.f); r1 = fmaxf(r1, 0.f);
            float* outp = g_x3 + ((size_t)c * L3_LEN + (t0 + tl0 + i)) * CNN_OUT + 2*pr;
            *(float2*)outp = make_float2(r0, r1);
        }
    }
}

// =====================================================================
// Kernel: gi precompute v3 — 2048 blocks (seq x 4 step-ranges), 192 thr.
// ~36+ warps/SM hides the per-dot latency chain that bounded v1/v2.
// gi[seq][step][row] = bih[row] + wih_row · x_step
// =====================================================================
__global__ __launch_bounds__(192) void k_gi(
    const float* __restrict__ wih_f, const float* __restrict__ bih_f,
    const float* __restrict__ wih_b, const float* __restrict__ bih_b)
{
    const int bx  = blockIdx.x;            // 0..2047
    const int seq = bx >> 2, chnk = bx & 3;
    const int dir = seq >> 8, c = seq & 255;
    const float* wih = dir ? wih_b : wih_f;
    const float* bih = dir ? bih_b : bih_f;
    const int row = threadIdx.x;           // 0..191
    const int s_base = chnk * GI_SPB;

    ULL wreg[16];
    {
        const ULL* p = (const ULL*)(wih + row * 32);
        #pragma unroll
        for (int i = 0; i < 16; i++) wreg[i] = p[i];
    }
    const float b = bih[row];
    float* out = g_gi + (size_t)seq * SEQ_STRIDE + row;
    const float* xbase = g_x3 + (size_t)c * (L3_LEN * CNN_OUT);

    __shared__ __align__(16) float xs[GI_SCH * 32];   // 25-step stage

    for (int sub = 0; sub < GI_SPB / GI_SCH; sub++) {
        const int s0 = s_base + sub * GI_SCH;
        __syncthreads();
        for (int i = row; i < GI_SCH * 8; i += 192) {     // 200 float4
            int ls = i >> 3, seg = i & 7;
            int tt = dir ? (L3_LEN - 1 - (s0 + ls)) : (s0 + ls);
            ((float4*)xs)[i] = ((const float4*)(xbase + tt * 32))[seg];
        }
        __syncthreads();
        #pragma unroll 5
        for (int ls = 0; ls < GI_SCH; ls++) {
            const ulonglong2* xp = (const ulonglong2*)(xs + ls * 32);
            ULL a0 = pk2(b, 0.f), a1 = pk2(0.f, 0.f);
            #pragma unroll
            for (int i = 0; i < 8; i++) {
                ulonglong2 u = xp[i];
                fma2(a0, wreg[2*i],   u.x);
                fma2(a1, wreg[2*i+1], u.y);
            }
            float lo, hi, v;
            upk2(a0, lo, hi); v  = lo + hi;
            upk2(a1, lo, hi); v += lo + hi;
            out[(size_t)(s0 + ls) * 192] = v;
        }
    }
}

// =====================================================================
// Kernel: GRU recurrence (measured-best k_gru2, verbatim from R13)
// =====================================================================
__global__ __launch_bounds__(128, 3) void k_gru2(
    const float* __restrict__ whh_f, const float* __restrict__ bhh_f,
    const float* __restrict__ whh_b, const float* __restrict__ bhh_b)
{
    const int blk = blockIdx.x;       // 0..255
    const int dir = blk & 1;
    const int cp  = blk >> 1;
    const int c0 = 2 * cp, c1 = 2 * cp + 1;
    const float* whh = dir ? whh_b : whh_f;
    const float* bhh = dir ? bhh_b : bhh_f;
    const int t = threadIdx.x;
    const int j = t >> 1, half = t & 1;

    ULL wr_[16], wz_[16], wn_[16];
    {
        const ULL* pr = (const ULL*)(whh + (j      ) * 64 + half * 32);
        const ULL* pz = (const ULL*)(whh + (j +  64) * 64 + half * 32);
        const ULL* pn = (const ULL*)(whh + (j + 128) * 64 + half * 32);
        #pragma unroll
        for (int i = 0; i < 16; i++) { wr_[i] = pr[i]; wz_[i] = pz[i]; wn_[i] = pn[i]; }
    }
    const float br = half ? 0.f : bhh[j];
    const float bz = half ? 0.f : bhh[j + 64];
    const float bn = half ? 0.f : bhh[j + 128];

    const float* giA = g_gi + (size_t)(dir * 256 + c0) * SEQ_STRIDE;
    const float* giB = g_gi + (size_t)(dir * 256 + c1) * SEQ_STRIDE;

    __shared__ __align__(16) float hs[2][2][64];          // [buf][seq][j]
    __shared__ __align__(16) float gsm[2][GCH][2][192];   // [buf][sl][seq][row]

    if (t < 64) { hs[0][0][t] = 0.f; hs[0][1][t] = 0.f; }

    #pragma unroll
    for (int k = 0; k < 3; k++) {
        int fi = t + k * 128;
        int sl = fi / 96, rem = fi % 96;
        int seq = rem / 48, r4 = rem % 48;
        const float* src = (seq ? giB : giA) + (size_t)sl * 192 + r4 * 4;
        *(float4*)&gsm[0][sl][seq][r4 * 4] = *(const float4*)src;
    }
    float hA = 0.f, hB = 0.f;
    __syncthreads();

    float4 pf[3];

    #pragma unroll 1
    for (int s = 0; s < L3_LEN; s++) {
        const int sl  = s & (GCH - 1);
        const int chk = s >> 2;
        const int buf = chk & 1;

        if (sl == 0 && chk + 1 < L3_LEN / GCH) {
            int step0 = (chk + 1) * GCH;
            #pragma unroll
            for (int k = 0; k < 3; k++) {
                int fi = t + k * 128;
                int psl = fi / 96, rem = fi % 96;
                int seq = rem / 48, r4 = rem % 48;
                const float* src = (seq ? giB : giA) + (size_t)(step0 + psl) * 192 + r4 * 4;
                pf[k] = *(const float4*)src;
            }
        }

        const ulonglong2* hpA = (const ulonglong2*)hs[s & 1][0] + half * 8;
        const ulonglong2* hpB = (const ulonglong2*)hs[s & 1][1] + half * 8;
        ULL arA = pk2(br, 0.f), azA = pk2(bz, 0.f), anA = pk2(bn, 0.f);
        ULL arA1 = pk2(0.f,0.f), azA1 = pk2(0.f,0.f), anA1 = pk2(0.f,0.f);
        ULL arB = pk2(br, 0.f), azB = pk2(bz, 0.f), anB = pk2(bn, 0.f);
        ULL arB1 = pk2(0.f,0.f), azB1 = pk2(0.f,0.f), anB1 = pk2(0.f,0.f);
        #pragma unroll
        for (int i = 0; i < 8; i++) {
            ulonglong2 uA = hpA[i];
            fma2(arA, wr_[2*i], uA.x);  fma2(arA1, wr_[2*i+1], uA.y);
            fma2(azA, wz_[2*i], uA.x);  fma2(azA1, wz_[2*i+1], uA.y);
            fma2(anA, wn_[2*i], uA.x);  fma2(anA1, wn_[2*i+1], uA.y);
            ulonglong2 uB = hpB[i];
            fma2(arB, wr_[2*i], uB.x);  fma2(arB1, wr_[2*i+1], uB.y);
            fma2(azB, wz_[2*i], uB.x);  fma2(azB1, wz_[2*i+1], uB.y);
            fma2(anB, wn_[2*i], uB.x);  fma2(anB1, wn_[2*i+1], uB.y);
        }
        float lo, hi;
        float ghrA, ghzA, ghnA, ghrB, ghzB, ghnB;
        upk2(arA, lo, hi);  ghrA  = lo + hi;  upk2(arA1, lo, hi); ghrA += lo + hi;
        upk2(azA, lo, hi);  ghzA  = lo + hi;  upk2(azA1, lo, hi); ghzA += lo + hi;
        upk2(anA, lo, hi);  ghnA  = lo + hi;  upk2(anA1, lo, hi); ghnA += lo + hi;
        upk2(arB, lo, hi);  ghrB  = lo + hi;  upk2(arB1, lo, hi); ghrB += lo + hi;
        upk2(azB, lo, hi);  ghzB  = lo + hi;  upk2(azB1, lo, hi); ghzB += lo + hi;
        upk2(anB, lo, hi);  ghnB  = lo + hi;  upk2(anB1, lo, hi); ghnB += lo + hi;

        ghrA += __shfl_xor_sync(0xffffffffu, ghrA, 1);
        ghzA += __shfl_xor_sync(0xffffffffu, ghzA, 1);
        ghnA += __shfl_xor_sync(0xffffffffu, ghnA, 1);
        ghrB += __shfl_xor_sync(0xffffffffu, ghrB, 1);
        ghzB += __shfl_xor_sync(0xffffffffu, ghzB, 1);
        ghnB += __shfl_xor_sync(0xffffffffu, ghnB, 1);

        if (half == 0) {
            const float* gA = gsm[buf][sl][0];
            const float* gB = gsm[buf][sl][1];
            float rA = sigmoid_f(gA[j] + ghrA);
            float zA = sigmoid_f(gA[j + 64] + ghzA);
            float nA = tanh_f(fmaf(rA, ghnA, gA[j + 128]));
            hA = fmaf(zA, hA - nA, nA);
            hs[(s + 1) & 1][0][j] = hA;
            float rB = sigmoid_f(gB[j] + ghrB);
            float zB = sigmoid_f(gB[j + 64] + ghzB);
            float nB = tanh_f(fmaf(rB, ghnB, gB[j + 128]));
            hB = fmaf(zB, hB - nB, nB);
            hs[(s + 1) & 1][1][j] = hB;
        }
        if (sl == GCH - 1 && chk + 1 < L3_LEN / GCH) {
            #pragma unroll
            for (int k = 0; k < 3; k++) {
                int fi = t + k * 128;
                int psl = fi / 96, rem = fi % 96;
                int seq = rem / 48, r4 = rem % 48;
                *(float4*)&gsm[buf ^ 1][psl][seq][r4 * 4] = pf[k];
            }
        }
        __syncthreads();
    }
    if (half == 0) {
        g_hn[c0 * 128 + dir * 64 + j] = hA;
        g_hn[c1 * 128 + dir * 64 + j] = hB;
    }
}

// =====================================================================
// per-row normalize
// =====================================================================
__global__ void k_norm()
{
    const int i = blockIdx.x, t = threadIdx.x;
    float v = g_hn[i * 128 + t];
    __shared__ float red[4], red2[4];
    float s = v;
    #pragma unroll
    for (int o = 16; o; o >>= 1) s += __shfl_xor_sync(0xffffffffu, s, o);
    if ((t & 31) == 0) red[t >> 5] = s;
    __syncthreads();
    float mean = (red[0] + red[1] + red[2] + red[3]) * (1.f / 128.f);
    float d = v - mean;
    float s2 = d * d;
    #pragma unroll
    for (int o = 16; o; o >>= 1) s2 += __shfl_xor_sync(0xffffffffu, s2, o);
    if ((t & 31) == 0) red2[t >> 5] = s2;
    __syncthreads();
    float var = (red2[0] + red2[1] + red2[2] + red2[3]) * (1.f / 127.f);
    g_xnT[t * N_CH + i] = d / (sqrtf(var) + 1e-6f);
}

// =====================================================================
// adjacency row + degree + M1
// =====================================================================
__global__ void k_adj(const float* __restrict__ g1w)
{
    const int i = blockIdx.x, t = threadIdx.x;
    __shared__ float xi[128], hi[128];
    __shared__ float degred[8];
    if (t < 128) { xi[t] = g_xnT[t * N_CH + i]; hi[t] = g_hn[i * 128 + t]; }
    __syncthreads();

    float acc = 0.f;
    #pragma unroll 4
    for (int k = 0; k < 128; k++) acc = fmaf(xi[k], g_xnT[k * N_CH + t], acc);
    acc *= (1.f / 128.f);
    float a = (fabsf(acc) > 0.7f) ? 1.f : 0.f;
    g_A[i * N_CH + t] = a;

    float s = a;
    #pragma unroll
    for (int o = 16; o; o >>= 1) s += __shfl_xor_sync(0xffffffffu, s, o);
    if ((t & 31) == 0) degred[t >> 5] = s;
    __syncthreads();
    if (t == 0) {
        float deg = 0.f;
        #pragma unroll
        for (int w = 0; w < 8; w++) deg += degred[w];
        g_dinv[i] = rsqrtf(fmaxf(deg, 1e-12f));
    }
    if (t < 32) {
        float m = 0.f;
        const float* wr = g1w + t * 128;
        #pragma unroll 4
        for (int k = 0; k < 128; k++) m = fmaf(hi[k], wr[k], m);
        g_M1[i * 32 + t] = m;
    }
}

// =====================================================================
__global__ void k_gcn1(const float* __restrict__ b1, const float* __restrict__ w2)
{
    const int i = blockIdx.x, t = threadIdx.x;
    const float di = g_dinv[i];
    float acc = 0.f;
    for (int j = 0; j < N_CH; j++) {
        float aij = g_A[i * N_CH + j];
        if (aij != 0.f) acc = fmaf(g_dinv[j], g_M1[j * 32 + t], acc);
    }
    float h1 = fmaxf(fmaf(di, acc, b1[t]), 0.f);
    __shared__ float h1s[32];
    h1s[t] = h1;
    __syncthreads();
    float m2 = 0.f;
    const float* wr = w2 + t * 32;
    #pragma unroll
    for (int o = 0; o < 32; o++) m2 = fmaf(h1s[o], wr[o], m2);
    g_M2[i * 32 + t] = m2;
}

__global__ void k_gcn2(const float* __restrict__ b2)
{
    const int i = blockIdx.x, t = threadIdx.x;
    const float di = g_dinv[i];
    float acc = 0.f;
    for (int j = 0; j < N_CH; j++) {
        float aij = g_A[i * N_CH + j];
        if (aij != 0.f) acc = fmaf(g_dinv[j], g_M2[j * 32 + t], acc);
    }
    g_h2[i * 32 + t] = fmaxf(fmaf(di, acc, b2[t]), 0.f);
}

__global__ void k_final(const float* __restrict__ cw, const float* __restrict__ cb,
                        float* __restrict__ out)
{
    const int t = threadIdx.x;
    float acc = 0.f;
    for (int i = 0; i < N_CH; i++) acc += g_h2[i * 32 + t];
    __shared__ float es[32];
    es[t] = acc * (1.f / 256.f);
    __syncthreads();
    if (t < 2) {
        float o = cb[t];
        #pragma unroll
        for (int k = 0; k < 32; k++) o = fmaf(es[k], cw[t * 32 + k], o);
        out[t] = o;
    }
}

// =====================================================================
extern "C" void kernel_launch(void* const* d_in, const int* in_sizes, int n_in,
                              void* d_out, int out_size)
{
    const float* data    = (const float*)d_in[0];
    const float* conv1_w = (const float*)d_in[1];
    const float* conv1_b = (const float*)d_in[2];
    const float* conv2_w = (const float*)d_in[3];
    const float* conv2_b = (const float*)d_in[4];
    const float* conv3_w = (const float*)d_in[5];
    const float* conv3_b = (const float*)d_in[6];
    const float* wih_f   = (const float*)d_in[7];
    const float* whh_f   = (const float*)d_in[8];
    const float* bih_f   = (const float*)d_in[9];
    const float* bhh_f   = (const float*)d_in[10];
    const float* wih_b   = (const float*)d_in[11];
    const float* whh_b   = (const float*)d_in[12];
    const float* bih_b   = (const float*)d_in[13];
    const float* bhh_b   = (const float*)d_in[14];
    const float* gcn1_w  = (const float*)d_in[15];
    const float* gcn1_b  = (const float*)d_in[16];
    const float* gcn2_w  = (const float*)d_in[17];
    const float* gcn2_b  = (const float*)d_in[18];
    const float* cls_w   = (const float*)d_in[19];
    const float* cls_b   = (const float*)d_in[20];

    // launch order: profiled slot #4 = k_gi (the changed kernel)
    k_prep_a<<<1, 256>>>(conv1_w, conv2_w);
    k_prep_b<<<1, 256>>>(conv3_w);
    k_conv_fused<<<N_CH * NTILE, 256>>>(data, conv1_b, conv2_b, conv3_b);
    k_gi<<<2048, 192>>>(wih_f, bih_f, wih_b, bih_b);
    k_gru2<<<256, 128>>>(whh_f, bhh_f, whh_b, bhh_b);
    k_norm<<<N_CH, 128>>>();
    k_adj<<<N_CH, 256>>>(gcn1_w);
    k_gcn1<<<N_CH, 32>>>(gcn1_b, gcn2_w);
    k_gcn2<<<N_CH, 32>>>(gcn2_b);
    k_final<<<1, 32>>>(cls_w, cls_b, (float*)d_out);
}

// round 17
// speedup vs baseline: 1.2097x; 1.0075x over previous
#include <cuda_runtime.h>
#include <math.h>

// ---------------- problem constants ----------------
#define N_CH   256
#define T_IN   100000
#define L1_LEN 20000
#define L2_LEN 4000
#define L3_LEN 800
#define CNN_OUT 32
#define GRU_H   64

// conv fused tiling
#define TILE   20
#define NTILE  (L3_LEN / TILE)
#define C2_SPAN 100
#define C1_SPAN 502

#define INP_ROW 508
#define C1_ROW  104
#define C2_ROW  20

// interleaved conv-weight table
#define W1I_OFF 0
#define W2I_OFF 88
#define W3I_OFF 984
#define WCONV_TOT 3544

// GRU gi chunking
#define GCH 4                      // steps per staged chunk (recurrence)
#define SEQ_STRIDE (800 * 192)     // floats per sequence in g_gi
#define GI_SPB 200                 // steps per gi block
#define GI_SCH 20                  // steps staged per smem sub-chunk

typedef unsigned long long ULL;

// ---------------- f32x2 helpers ----------------
__device__ __forceinline__ ULL pk2(float a, float b) {
    ULL r; asm("mov.b64 %0, {%1, %2};" : "=l"(r) : "f"(a), "f"(b)); return r;
}
__device__ __forceinline__ void upk2(ULL v, float &a, float &b) {
    asm("mov.b64 {%0, %1}, %2;" : "=f"(a), "=f"(b) : "l"(v));
}
__device__ __forceinline__ void fma2(ULL &d, ULL a, ULL b) {
    asm("fma.rn.f32x2 %0, %1, %2, %0;" : "+l"(d) : "l"(a), "l"(b));
}

__device__ __forceinline__ float sigmoid_f(float x) {
    return __fdividef(1.f, 1.f + __expf(-x));
}
__device__ __forceinline__ float tanh_f(float x) {
    return 1.f - __fdividef(2.f, __expf(2.f * x) + 1.f);
}

// ---------------- scratch (static device, no allocation) ----------------
__device__ __align__(16) float g_wconv[WCONV_TOT];
__device__ __align__(16) float g_x3[N_CH * L3_LEN * CNN_OUT];   // conv3 out [c][t][f]
__device__ __align__(16) float g_gi[512 * SEQ_STRIDE];          // gi[seq][step][row]
__device__ float g_hn[N_CH * 128];
__device__ float g_xnT[128 * N_CH];
__device__ float g_A[N_CH * N_CH];
__device__ float g_dinv[N_CH];
__device__ float g_M1[N_CH * 32];
__device__ float g_M2[N_CH * 32];
__device__ float g_h2[N_CH * 32];

// =====================================================================
// Prep kernels (2 so ncu slot #4 = k_gi)
// =====================================================================
__global__ void k_prep_a(const float* __restrict__ w1, const float* __restrict__ w2)
{
    const int tid = threadIdx.x;
    if (tid < 44) {
        int pr = tid / 11, k = tid - pr * 11;
        g_wconv[W1I_OFF + 2*tid]     = w1[(2*pr)   * 11 + k];
        g_wconv[W1I_OFF + 2*tid + 1] = w1[(2*pr+1) * 11 + k];
    }
    for (int i = tid; i < 448; i += 256) {
        int k = i % 7, ic = (i / 7) % 8, pr = i / 56;
        g_wconv[W2I_OFF + 2*i]     = w2[((2*pr)   * 8 + ic) * 7 + k];
        g_wconv[W2I_OFF + 2*i + 1] = w2[((2*pr+1) * 8 + ic) * 7 + k];
    }
}
__global__ void k_prep_b(const float* __restrict__ w3)
{
    const int tid = threadIdx.x;
    for (int i = tid; i < 1280; i += 256) {
        int k = i % 5, ic = (i / 5) % 16, pr = i / 80;
        g_wconv[W3I_OFF + 2*i]     = w3[((2*pr)   * 16 + ic) * 5 + k];
        g_wconv[W3I_OFF + 2*i + 1] = w3[((2*pr+1) * 16 + ic) * 5 + k];
    }
}

// =====================================================================
// Kernel: fused conv1+conv2+conv3 (measured, unchanged)
// =====================================================================
#define SM_INP  0
#define SM_C1P  (SM_INP + 5*INP_ROW)
#define SM_C2P  (SM_C1P + 5*8*C1_ROW)
#define SM_W1   (SM_C2P + 5*16*C2_ROW)
#define SM_W2   (SM_W1 + 88)
#define SM_W3   (SM_W2 + 896)
#define SM_B1   (SM_W3 + 2560)
#define SM_B2   (SM_B1 + 8)
#define SM_B3   (SM_B2 + 16)
#define SM_TOT  (SM_B3 + 32)

__global__ __launch_bounds__(256) void k_conv_fused(
    const float* __restrict__ data,
    const float* __restrict__ b1,
    const float* __restrict__ b2,
    const float* __restrict__ b3)
{
    __shared__ __align__(16) float sm[SM_TOT];

    const int tid = threadIdx.x;
    const int c   = blockIdx.x / NTILE;
    const int t0  = (blockIdx.x % NTILE) * TILE;

    {
        const float4* src = (const float4*)g_wconv;
        float4* dst = (float4*)(sm + SM_W1);
        for (int i = tid; i < WCONV_TOT / 4; i += 256) dst[i] = src[i];
    }
    if (tid < 8)  sm[SM_B1 + tid] = b1[tid];
    if (tid < 16) sm[SM_B2 + tid] = b2[tid];
    if (tid < 32) sm[SM_B3 + tid] = b3[tid];

    {
        const float* dch = data + (size_t)c * T_IN;
        const int base = 125 * t0 - 70;
        for (int i = tid; i < 5 * INP_ROW; i += 256) {
            int g = base + i;
            float v = (g >= 0 && g < T_IN) ? dch[g] : 0.f;
            sm[SM_INP + (i % 5) * INP_ROW + (i / 5)] = v;
        }
    }
    __syncthreads();

    // conv1
    {
        const int grp = tid >> 6;
        const int l64 = tid & 63;
        ULL wreg[11];
        {
            const ULL* wp = (const ULL*)(sm + SM_W1) + grp * 11;
            #pragma unroll
            for (int k = 0; k < 11; k++) wreg[k] = wp[k];
        }
        const ULL bpair = pk2(sm[SM_B1 + 2*grp], sm[SM_B1 + 2*grp + 1]);
        const int q0g = 25 * t0 - 13;

        #pragma unroll
        for (int it = 0; it < 2; it++) {
            int m = 64 * it + l64;
            int q0 = 4 * m;
            if (q0 >= C1_SPAN) break;
            float p0v[6], p1v[6], p2v[6], p3v[6], p4v[6];
            {
                const float* r0 = sm + SM_INP + 0 * INP_ROW + q0;
                const float* r1 = sm + SM_INP + 1 * INP_ROW + q0;
                const float* r2 = sm + SM_INP + 2 * INP_ROW + q0;
                const float* r3 = sm + SM_INP + 3 * INP_ROW + q0;
                const float* r4 = sm + SM_INP + 4 * INP_ROW + q0;
                float4 v;
                v = *(const float4*)r0; p0v[0]=v.x; p0v[1]=v.y; p0v[2]=v.z; p0v[3]=v.w; p0v[4]=r0[4]; p0v[5]=r0[5];
                v = *(const float4*)r1; p1v[0]=v.x; p1v[1]=v.y; p1v[2]=v.z; p1v[3]=v.w; p1v[4]=r1[4];
                v = *(const float4*)r2; p2v[0]=v.x; p2v[1]=v.y; p2v[2]=v.z; p2v[3]=v.w; p2v[4]=r2[4];
                v = *(const float4*)r3; p3v[0]=v.x; p3v[1]=v.y; p3v[2]=v.z; p3v[3]=v.w; p3v[4]=r3[4];
                v = *(const float4*)r4; p4v[0]=v.x; p4v[1]=v.y; p4v[2]=v.z; p4v[3]=v.w; p4v[4]=r4[4];
            }
            #pragma unroll
            for (int i = 0; i < 4; i++) {
                int q = q0 + i;
                if (q >= C1_SPAN) break;
                ULL acc = bpair;
                fma2(acc, wreg[0],  pk2(p0v[i],   p0v[i]));
                fma2(acc, wreg[1],  pk2(p1v[i],   p1v[i]));
                fma2(acc, wreg[2],  pk2(p2v[i],   p2v[i]));
                fma2(acc, wreg[3],  pk2(p3v[i],   p3v[i]));
                fma2(acc, wreg[4],  pk2(p4v[i],   p4v[i]));
                fma2(acc, wreg[5],  pk2(p0v[i+1], p0v[i+1]));
                fma2(acc, wreg[6],  pk2(p1v[i+1], p1v[i+1]));
                fma2(acc, wreg[7],  pk2(p2v[i+1], p2v[i+1]));
                fma2(acc, wreg[8],  pk2(p3v[i+1], p3v[i+1]));
                fma2(acc, wreg[9],  pk2(p4v[i+1], p4v[i+1]));
                fma2(acc, wreg[10], pk2(p0v[i+2], p0v[i+2]));
                float r0, r1; upk2(acc, r0, r1);
                bool ok = ((unsigned)(q0g + q) < L1_LEN);
                r0 = ok ? fmaxf(r0, 0.f) : 0.f;
                r1 = ok ? fmaxf(r1, 0.f) : 0.f;
                int ph = q % 5, j = q / 5;
                sm[SM_C1P + (ph * 8 + 2*grp)     * C1_ROW + j] = r0;
                sm[SM_C1P + (ph * 8 + 2*grp + 1) * C1_ROW + j] = r1;
            }
        }
    }
    __syncthreads();

    // conv2
    {
        const int pr = tid >> 5;
        const int m  = tid & 31;
        if (m < 25) {
            const int p0 = 4 * m;
            ULL acc[4];
            const ULL bpair = pk2(sm[SM_B2 + 2*pr], sm[SM_B2 + 2*pr + 1]);
            #pragma unroll
            for (int i = 0; i < 4; i++) acc[i] = bpair;
            const ULL* wbase = (const ULL*)(sm + SM_W2) + pr * 56;
            #pragma unroll
            for (int ic = 0; ic < 8; ic++) {
                ULL wreg[7];
                #pragma unroll
                for (int k = 0; k < 7; k++) wreg[k] = wbase[ic * 7 + k];
                float p0v[5], p1v[5], p2v[4], p3v[4], p4v[4];
                {
                    const float* r0 = sm + SM_C1P + (0 * 8 + ic) * C1_ROW + p0;
                    const float* r1 = sm + SM_C1P + (1 * 8 + ic) * C1_ROW + p0;
                    const float* r2 = sm + SM_C1P + (2 * 8 + ic) * C1_ROW + p0;
                    const float* r3 = sm + SM_C1P + (3 * 8 + ic) * C1_ROW + p0;
                    const float* r4 = sm + SM_C1P + (4 * 8 + ic) * C1_ROW + p0;
                    float4 v;
                    v = *(const float4*)r0; p0v[0]=v.x; p0v[1]=v.y; p0v[2]=v.z; p0v[3]=v.w; p0v[4]=r0[4];
                    v = *(const float4*)r1; p1v[0]=v.x; p1v[1]=v.y; p1v[2]=v.z; p1v[3]=v.w; p1v[4]=r1[4];
                    v = *(const float4*)r2; p2v[0]=v.x; p2v[1]=v.y; p2v[2]=v.z; p2v[3]=v.w;
                    v = *(const float4*)r3; p3v[0]=v.x; p3v[1]=v.y; p3v[2]=v.z; p3v[3]=v.w;
                    v = *(const float4*)r4; p4v[0]=v.x; p4v[1]=v.y; p4v[2]=v.z; p4v[3]=v.w;
                }
                #pragma unroll
                for (int i = 0; i < 4; i++) {
                    fma2(acc[i], wreg[0], pk2(p0v[i],   p0v[i]));
                    fma2(acc[i], wreg[1], pk2(p1v[i],   p1v[i]));
                    fma2(acc[i], wreg[2], pk2(p2v[i],   p2v[i]));
                    fma2(acc[i], wreg[3], pk2(p3v[i],   p3v[i]));
                    fma2(acc[i], wreg[4], pk2(p4v[i],   p4v[i]));
                    fma2(acc[i], wreg[5], pk2(p0v[i+1], p0v[i+1]));
                    fma2(acc[i], wreg[6], pk2(p1v[i+1], p1v[i+1]));
                }
            }
            const int p0g = 5 * t0 - 2;
            #pragma unroll
            for (int i = 0; i < 4; i++) {
                int p = p0 + i;
                float r0, r1; upk2(acc[i], r0, r1);
                bool ok = ((unsigned)(p0g + p) < L2_LEN);
                r0 = ok ? fmaxf(r0, 0.f) : 0.f;
                r1 = ok ? fmaxf(r1, 0.f) : 0.f;
                int ph = p % 5, j = p / 5;
                sm[SM_C2P + (ph * 16 + 2*pr)     * C2_ROW + j] = r0;
                sm[SM_C2P + (ph * 16 + 2*pr + 1) * C2_ROW + j] = r1;
            }
        }
    }
    __syncthreads();

    // conv3
    if (tid < 80) {
        const int pr  = tid / 5;
        const int tl0 = (tid % 5) * 4;
        ULL acc[4];
        const ULL bpair = pk2(sm[SM_B3 + 2*pr], sm[SM_B3 + 2*pr + 1]);
        #pragma unroll
        for (int i = 0; i < 4; i++) acc[i] = bpair;
        const ULL* wbase = (const ULL*)(sm + SM_W3) + pr * 80;
        #pragma unroll
        for (int ic = 0; ic < 16; ic++) {
            ULL wreg[5];
            #pragma unroll
            for (int k = 0; k < 5; k++) wreg[k] = wbase[ic * 5 + k];
            float4 P0 = *(const float4*)(sm + SM_C2P + (0 * 16 + ic) * C2_ROW + tl0);
            float4 P1 = *(const float4*)(sm + SM_C2P + (1 * 16 + ic) * C2_ROW + tl0);
            float4 P2 = *(const float4*)(sm + SM_C2P + (2 * 16 + ic) * C2_ROW + tl0);
            float4 P3 = *(const float4*)(sm + SM_C2P + (3 * 16 + ic) * C2_ROW + tl0);
            float4 P4 = *(const float4*)(sm + SM_C2P + (4 * 16 + ic) * C2_ROW + tl0);
            const float* a0 = (const float*)&P0;
            const float* a1 = (const float*)&P1;
            const float* a2 = (const float*)&P2;
            const float* a3 = (const float*)&P3;
            const float* a4 = (const float*)&P4;
            #pragma unroll
            for (int i = 0; i < 4; i++) {
                fma2(acc[i], wreg[0], pk2(a0[i], a0[i]));
                fma2(acc[i], wreg[1], pk2(a1[i], a1[i]));
                fma2(acc[i], wreg[2], pk2(a2[i], a2[i]));
                fma2(acc[i], wreg[3], pk2(a3[i], a3[i]));
                fma2(acc[i], wreg[4], pk2(a4[i], a4[i]));
            }
        }
        #pragma unroll
        for (int i = 0; i < 4; i++) {
            float r0, r1; upk2(acc[i], r0, r1);
            r0 = fmaxf(r0, 0.f); r1 = fmaxf(r1, 0.f);
            float* outp = g_x3 + ((size_t)c * L3_LEN + (t0 + tl0 + i)) * CNN_OUT + 2*pr;
            *(float2*)outp = make_float2(r0, r1);
        }
    }
}

// =====================================================================
// Kernel: gi precompute v4 — TWO rows per thread sharing x loads
// (halves LDS per FFMA2). 2048 blocks x 192 thr; thread (grp,k):
// rows 2k,2k+1; grp 0/1 handle steps [0,10)/[10,20) of each sub-chunk.
// =====================================================================
__global__ __launch_bounds__(192) void k_gi(
    const float* __restrict__ wih_f, const float* __restrict__ bih_f,
    const float* __restrict__ wih_b, const float* __restrict__ bih_b)
{
    const int bx  = blockIdx.x;            // 0..2047
    const int seq = bx >> 2, rng = bx & 3;
    const int dir = seq >> 8, c = seq & 255;
    const float* wih = dir ? wih_b : wih_f;
    const float* bih = dir ? bih_b : bih_f;
    const int t   = threadIdx.x;           // 0..191
    const int grp = t / 96, k = t - grp * 96;
    const int r0 = 2 * k, r1 = 2 * k + 1;
    const int s_base = rng * GI_SPB;

    ULL wA[16], wB[16];
    {
        const ULL* pA = (const ULL*)(wih + r0 * 32);
        const ULL* pB = (const ULL*)(wih + r1 * 32);
        #pragma unroll
        for (int i = 0; i < 16; i++) { wA[i] = pA[i]; wB[i] = pB[i]; }
    }
    const float bA = bih[r0], bB = bih[r1];
    float* out = g_gi + (size_t)seq * SEQ_STRIDE + r0;
    const float* xbase = g_x3 + (size_t)c * (L3_LEN * CNN_OUT);

    __shared__ __align__(16) float xs[GI_SCH * 32];   // 20-step stage

    for (int sub = 0; sub < GI_SPB / GI_SCH; sub++) {
        const int s0 = s_base + sub * GI_SCH;
        __syncthreads();
        if (t < GI_SCH * 8) {                         // 160 float4
            int ls = t >> 3, seg = t & 7;
            int tt = dir ? (L3_LEN - 1 - (s0 + ls)) : (s0 + ls);
            ((float4*)xs)[t] = ((const float4*)(xbase + tt * 32))[seg];
        }
        __syncthreads();
        const int l0 = grp * (GI_SCH / 2);
        #pragma unroll 5
        for (int li = 0; li < GI_SCH / 2; li++) {
            const int ls = l0 + li;
            const ulonglong2* xp = (const ulonglong2*)(xs + ls * 32);
            ULL a0 = pk2(bA, 0.f), a1 = pk2(0.f, 0.f);
            ULL b0 = pk2(bB, 0.f), b1 = pk2(0.f, 0.f);
            #pragma unroll
            for (int i = 0; i < 8; i++) {
                ulonglong2 u = xp[i];
                fma2(a0, wA[2*i],   u.x);
                fma2(a1, wA[2*i+1], u.y);
                fma2(b0, wB[2*i],   u.x);
                fma2(b1, wB[2*i+1], u.y);
            }
            float lo, hi, vA, vB;
            upk2(a0, lo, hi); vA  = lo + hi;
            upk2(a1, lo, hi); vA += lo + hi;
            upk2(b0, lo, hi); vB  = lo + hi;
            upk2(b1, lo, hi); vB += lo + hi;
            *(float2*)(out + (size_t)(s0 + ls) * 192) = make_float2(vA, vB);
        }
    }
}

// =====================================================================
// Kernel: GRU recurrence — k_gru2 with the gate-update split across
// halves (half 0 updates seq A, half 1 updates seq B in parallel).
// =====================================================================
__global__ __launch_bounds__(128, 3) void k_gru2(
    const float* __restrict__ whh_f, const float* __restrict__ bhh_f,
    const float* __restrict__ whh_b, const float* __restrict__ bhh_b)
{
    const int blk = blockIdx.x;       // 0..255
    const int dir = blk & 1;
    const int cp  = blk >> 1;
    const int c0 = 2 * cp, c1 = 2 * cp + 1;
    const float* whh = dir ? whh_b : whh_f;
    const float* bhh = dir ? bhh_b : bhh_f;
    const int t = threadIdx.x;
    const int j = t >> 1, half = t & 1;

    ULL wr_[16], wz_[16], wn_[16];
    {
        const ULL* pr = (const ULL*)(whh + (j      ) * 64 + half * 32);
        const ULL* pz = (const ULL*)(whh + (j +  64) * 64 + half * 32);
        const ULL* pn = (const ULL*)(whh + (j + 128) * 64 + half * 32);
        #pragma unroll
        for (int i = 0; i < 16; i++) { wr_[i] = pr[i]; wz_[i] = pz[i]; wn_[i] = pn[i]; }
    }
    const float br = half ? 0.f : bhh[j];
    const float bz = half ? 0.f : bhh[j + 64];
    const float bn = half ? 0.f : bhh[j + 128];

    const float* giA = g_gi + (size_t)(dir * 256 + c0) * SEQ_STRIDE;
    const float* giB = g_gi + (size_t)(dir * 256 + c1) * SEQ_STRIDE;

    __shared__ __align__(16) float hs[2][2][64];          // [buf][seq][j]
    __shared__ __align__(16) float gsm[2][GCH][2][192];   // [buf][sl][seq][row]

    if (t < 64) { hs[0][0][t] = 0.f; hs[0][1][t] = 0.f; }

    #pragma unroll
    for (int k = 0; k < 3; k++) {
        int fi = t + k * 128;
        int sl = fi / 96, rem = fi % 96;
        int seq = rem / 48, r4 = rem % 48;
        const float* src = (seq ? giB : giA) + (size_t)sl * 192 + r4 * 4;
        *(float4*)&gsm[0][sl][seq][r4 * 4] = *(const float4*)src;
    }
    float hA = 0.f, hB = 0.f;
    __syncthreads();

    float4 pf[3];

    #pragma unroll 1
    for (int s = 0; s < L3_LEN; s++) {
        const int sl  = s & (GCH - 1);
        const int chk = s >> 2;
        const int buf = chk & 1;

        if (sl == 0 && chk + 1 < L3_LEN / GCH) {
            int step0 = (chk + 1) * GCH;
            #pragma unroll
            for (int k = 0; k < 3; k++) {
                int fi = t + k * 128;
                int psl = fi / 96, rem = fi % 96;
                int seq = rem / 48, r4 = rem % 48;
                const float* src = (seq ? giB : giA) + (size_t)(step0 + psl) * 192 + r4 * 4;
                pf[k] = *(const float4*)src;
            }
        }

        const ulonglong2* hpA = (const ulonglong2*)hs[s & 1][0] + half * 8;
        const ulonglong2* hpB = (const ulonglong2*)hs[s & 1][1] + half * 8;
        ULL arA = pk2(br, 0.f), azA = pk2(bz, 0.f), anA = pk2(bn, 0.f);
        ULL arA1 = pk2(0.f,0.f), azA1 = pk2(0.f,0.f), anA1 = pk2(0.f,0.f);
        ULL arB = pk2(br, 0.f), azB = pk2(bz, 0.f), anB = pk2(bn, 0.f);
        ULL arB1 = pk2(0.f,0.f), azB1 = pk2(0.f,0.f), anB1 = pk2(0.f,0.f);
        #pragma unroll
        for (int i = 0; i < 8; i++) {
            ulonglong2 uA = hpA[i];
            fma2(arA, wr_[2*i], uA.x);  fma2(arA1, wr_[2*i+1], uA.y);
            fma2(azA, wz_[2*i], uA.x);  fma2(azA1, wz_[2*i+1], uA.y);
            fma2(anA, wn_[2*i], uA.x);  fma2(anA1, wn_[2*i+1], uA.y);
            ulonglong2 uB = hpB[i];
            fma2(arB, wr_[2*i], uB.x);  fma2(arB1, wr_[2*i+1], uB.y);
            fma2(azB, wz_[2*i], uB.x);  fma2(azB1, wz_[2*i+1], uB.y);
            fma2(anB, wn_[2*i], uB.x);  fma2(anB1, wn_[2*i+1], uB.y);
        }
        float lo, hi;
        float ghrA, ghzA, ghnA, ghrB, ghzB, ghnB;
        upk2(arA, lo, hi);  ghrA  = lo + hi;  upk2(arA1, lo, hi); ghrA += lo + hi;
        upk2(azA, lo, hi);  ghzA  = lo + hi;  upk2(azA1, lo, hi); ghzA += lo + hi;
        upk2(anA, lo, hi);  ghnA  = lo + hi;  upk2(anA1, lo, hi); ghnA += lo + hi;
        upk2(arB, lo, hi);  ghrB  = lo + hi;  upk2(arB1, lo, hi); ghrB += lo + hi;
        upk2(azB, lo, hi);  ghzB  = lo + hi;  upk2(azB1, lo, hi); ghzB += lo + hi;
        upk2(anB, lo, hi);  ghnB  = lo + hi;  upk2(anB1, lo, hi); ghnB += lo + hi;

        ghrA += __shfl_xor_sync(0xffffffffu, ghrA, 1);
        ghzA += __shfl_xor_sync(0xffffffffu, ghzA, 1);
        ghnA += __shfl_xor_sync(0xffffffffu, ghnA, 1);
        ghrB += __shfl_xor_sync(0xffffffffu, ghrB, 1);
        ghzB += __shfl_xor_sync(0xffffffffu, ghzB, 1);
        ghnB += __shfl_xor_sync(0xffffffffu, ghnB, 1);

        // split update: half 0 -> seq A, half 1 -> seq B (parallel chains)
        if (half == 0) {
            const float* gA = gsm[buf][sl][0];
            float rA = sigmoid_f(gA[j] + ghrA);
            float zA = sigmoid_f(gA[j + 64] + ghzA);
            float nA = tanh_f(fmaf(rA, ghnA, gA[j + 128]));
            hA = fmaf(zA, hA - nA, nA);
            hs[(s + 1) & 1][0][j] = hA;
        } else {
            const float* gB = gsm[buf][sl][1];
            float rB = sigmoid_f(gB[j] + ghrB);
            float zB = sigmoid_f(gB[j + 64] + ghzB);
            float nB = tanh_f(fmaf(rB, ghnB, gB[j + 128]));
            hB = fmaf(zB, hB - nB, nB);
            hs[(s + 1) & 1][1][j] = hB;
        }
        if (sl == GCH - 1 && chk + 1 < L3_LEN / GCH) {
            #pragma unroll
            for (int k = 0; k < 3; k++) {
                int fi = t + k * 128;
                int psl = fi / 96, rem = fi % 96;
                int seq = rem / 48, r4 = rem % 48;
                *(float4*)&gsm[buf ^ 1][psl][seq][r4 * 4] = pf[k];
            }
        }
        __syncthreads();
    }
    if (half == 0) g_hn[c0 * 128 + dir * 64 + j] = hA;
    else           g_hn[c1 * 128 + dir * 64 + j] = hB;
}

// =====================================================================
// per-row normalize
// =====================================================================
__global__ void k_norm()
{
    const int i = blockIdx.x, t = threadIdx.x;
    float v = g_hn[i * 128 + t];
    __shared__ float red[4], red2[4];
    float s = v;
    #pragma unroll
    for (int o = 16; o; o >>= 1) s += __shfl_xor_sync(0xffffffffu, s, o);
    if ((t & 31) == 0) red[t >> 5] = s;
    __syncthreads();
    float mean = (red[0] + red[1] + red[2] + red[3]) * (1.f / 128.f);
    float d = v - mean;
    float s2 = d * d;
    #pragma unroll
    for (int o = 16; o; o >>= 1) s2 += __shfl_xor_sync(0xffffffffu, s2, o);
    if ((t & 31) == 0) red2[t >> 5] = s2;
    __syncthreads();
    float var = (red2[0] + red2[1] + red2[2] + red2[3]) * (1.f / 127.f);
    g_xnT[t * N_CH + i] = d / (sqrtf(var) + 1e-6f);
}

// =====================================================================
// adjacency row + degree + M1
// =====================================================================
__global__ void k_adj(const float* __restrict__ g1w)
{
    const int i = blockIdx.x, t = threadIdx.x;
    __shared__ float xi[128], hi[128];
    __shared__ float degred[8];
    if (t < 128) { xi[t] = g_xnT[t * N_CH + i]; hi[t] = g_hn[i * 128 + t]; }
    __syncthreads();

    float acc = 0.f;
    #pragma unroll 4
    for (int k = 0; k < 128; k++) acc = fmaf(xi[k], g_xnT[k * N_CH + t], acc);
    acc *= (1.f / 128.f);
    float a = (fabsf(acc) > 0.7f) ? 1.f : 0.f;
    g_A[i * N_CH + t] = a;

    float s = a;
    #pragma unroll
    for (int o = 16; o; o >>= 1) s += __shfl_xor_sync(0xffffffffu, s, o);
    if ((t & 31) == 0) degred[t >> 5] = s;
    __syncthreads();
    if (t == 0) {
        float deg = 0.f;
        #pragma unroll
        for (int w = 0; w < 8; w++) deg += degred[w];
        g_dinv[i] = rsqrtf(fmaxf(deg, 1e-12f));
    }
    if (t < 32) {
        float m = 0.f;
        const float* wr = g1w + t * 128;
        #pragma unroll 4
        for (int k = 0; k < 128; k++) m = fmaf(hi[k], wr[k], m);
        g_M1[i * 32 + t] = m;
    }
}

// =====================================================================
__global__ void k_gcn1(const float* __restrict__ b1, const float* __restrict__ w2)
{
    const int i = blockIdx.x, t = threadIdx.x;
    const float di = g_dinv[i];
    float acc = 0.f;
    for (int j = 0; j < N_CH; j++) {
        float aij = g_A[i * N_CH + j];
        if (aij != 0.f) acc = fmaf(g_dinv[j], g_M1[j * 32 + t], acc);
    }
    float h1 = fmaxf(fmaf(di, acc, b1[t]), 0.f);
    __shared__ float h1s[32];
    h1s[t] = h1;
    __syncthreads();
    float m2 = 0.f;
    const float* wr = w2 + t * 32;
    #pragma unroll
    for (int o = 0; o < 32; o++) m2 = fmaf(h1s[o], wr[o], m2);
    g_M2[i * 32 + t] = m2;
}

__global__ void k_gcn2(const float* __restrict__ b2)
{
    const int i = blockIdx.x, t = threadIdx.x;
    const float di = g_dinv[i];
    float acc = 0.f;
    for (int j = 0; j < N_CH; j++) {
        float aij = g_A[i * N_CH + j];
        if (aij != 0.f) acc = fmaf(g_dinv[j], g_M2[j * 32 + t], acc);
    }
    g_h2[i * 32 + t] = fmaxf(fmaf(di, acc, b2[t]), 0.f);
}

__global__ void k_final(const float* __restrict__ cw, const float* __restrict__ cb,
                        float* __restrict__ out)
{
    const int t = threadIdx.x;
    float acc = 0.f;
    for (int i = 0; i < N_CH; i++) acc += g_h2[i * 32 + t];
    __shared__ float es[32];
    es[t] = acc * (1.f / 256.f);
    __syncthreads();
    if (t < 2) {
        float o = cb[t];
        #pragma unroll
        for (int k = 0; k < 32; k++) o = fmaf(es[k], cw[t * 32 + k], o);
        out[t] = o;
    }
}

// =====================================================================
extern "C" void kernel_launch(void* const* d_in, const int* in_sizes, int n_in,
                              void* d_out, int out_size)
{
    const float* data    = (const float*)d_in[0];
    const float* conv1_w = (const float*)d_in[1];
    const float* conv1_b = (const float*)d_in[2];
    const float* conv2_w = (const float*)d_in[3];
    const float* conv2_b = (const float*)d_in[4];
    const float* conv3_w = (const float*)d_in[5];
    const float* conv3_b = (const float*)d_in[6];
    const float* wih_f   = (const float*)d_in[7];
    const float* whh_f   = (const float*)d_in[8];
    const float* bih_f   = (const float*)d_in[9];
    const float* bhh_f   = (const float*)d_in[10];
    const float* wih_b   = (const float*)d_in[11];
    const float* whh_b   = (const float*)d_in[12];
    const float* bih_b   = (const float*)d_in[13];
    const float* bhh_b   = (const float*)d_in[14];
    const float* gcn1_w  = (const float*)d_in[15];
    const float* gcn1_b  = (const float*)d_in[16];
    const float* gcn2_w  = (const float*)d_in[17];
    const float* gcn2_b  = (const float*)d_in[18];
    const float* cls_w   = (const float*)d_in[19];
    const float* cls_b   = (const float*)d_in[20];

    // launch order: profiled slot #4 = k_gi
    k_prep_a<<<1, 256>>>(conv1_w, conv2_w);
    k_prep_b<<<1, 256>>>(conv3_w);
    k_conv_fused<<<N_CH * NTILE, 256>>>(data, conv1_b, conv2_b, conv3_b);
    k_gi<<<2048, 192>>>(wih_f, bih_f, wih_b, bih_b);
    k_gru2<<<256, 128>>>(whh_f, bhh_f, whh_b, bhh_b);
    k_norm<<<N_CH, 128>>>();
    k_adj<<<N_CH, 256>>>(gcn1_w);
    k_gcn1<<<N_CH, 32>>>(gcn1_b, gcn2_w);
    k_gcn2<<<N_CH, 32>>>(gcn2_b);
    k_final<<<1, 32>>>(cls_w, cls_b, (float*)d_out);
}